// round 3
// baseline (speedup 1.0000x reference)
#include <cuda_runtime.h>
#include <cstdint>
#include <math_constants.h>

// ============================================================================
// KineticOptimalDiscreteEulerSolver — collapsed form.
//
// Reference builds an O(N*V^2) jump-rate matrix; the algebra collapses:
//   p_t[i]*p_dot[j] - p_dot[i]*p_t[j] = sp_i*delta_j - delta_i*sp_j
// (all t-terms cancel). With delta = one_hot(x1), the selected output row is
// zero except (when x1 != x_t):
//   out[x1] = +u, out[x_t] = -u,
//   u = max(p_t[xt]*pd[x1] - pd[xt]*p_t[x1], 0) / (p_t[x1] + EPS)
// and identically zero when x1 == x_t.
//
// x1 must match jax.random.categorical(jax.random.key(1), logits) under the
// MODERN (partitionable) threefry stream (jax_threefry_partitionable=True,
// default in jax >= 0.5):
//   per-element 64-bit counter = flat index idx:
//     (o0, o1) = threefry2x32(key=(0,1), counter=(idx>>32, idx&0xffffffff))
//     bits     = o0 ^ o1
//   uniform = max(tiny, bitcast((bits>>9) | 0x3f800000) - 1)
//   gumbel  = -log(-log(uniform))
//   x1      = argmax(logits + gumbel), first-index tie-break.
// ============================================================================

#define TINYF 1.17549435e-38f
#define EPSF  1e-8f

__device__ __forceinline__ uint32_t rotl32(uint32_t x, int r) {
    return (x << r) | (x >> (32 - r));
}

// Threefry-2x32, 20 rounds, key (0, 1)  [jax.random.key(1) -> raw (0,1)]
__device__ __forceinline__ void threefry2x32_key01(uint32_t c0, uint32_t c1,
                                                   uint32_t& o0, uint32_t& o1) {
    const uint32_t ks0 = 0u;
    const uint32_t ks1 = 1u;
    const uint32_t ks2 = 0x1BD11BDAu ^ ks0 ^ ks1;  // 0x1BD11BDB
    uint32_t x0 = c0 + ks0;
    uint32_t x1 = c1 + ks1;

#define TF_ROUND(r) { x0 += x1; x1 = rotl32(x1, r); x1 ^= x0; }
#define TF_G0 TF_ROUND(13) TF_ROUND(15) TF_ROUND(26) TF_ROUND(6)
#define TF_G1 TF_ROUND(17) TF_ROUND(29) TF_ROUND(16) TF_ROUND(24)

    TF_G0  x0 += ks1; x1 += ks2 + 1u;
    TF_G1  x0 += ks2; x1 += ks0 + 2u;
    TF_G0  x0 += ks0; x1 += ks1 + 3u;
    TF_G1  x0 += ks1; x1 += ks2 + 4u;
    TF_G0  x0 += ks2; x1 += ks0 + 5u;

#undef TF_ROUND
#undef TF_G0
#undef TF_G1
    o0 = x0;
    o1 = x1;
}

// Partitionable-threefry gumbel for flat element index idx (< 2^32 here):
// counter = (hi=0, lo=idx); 32-bit output word = o0 ^ o1.
__device__ __forceinline__ float jax_gumbel_part(uint32_t idx) {
    uint32_t o0, o1;
    threefry2x32_key01(0u, idx, o0, o1);
    uint32_t bits = o0 ^ o1;
    float f = __uint_as_float((bits >> 9) | 0x3f800000u) - 1.0f;
    float u = fmaxf(TINYF, f);   // f*(1-tiny)+tiny == f in fp32 for f>0; 0 -> tiny
    return -logf(-logf(u));
}

__global__ void kinetic_euler_kernel(const float* __restrict__ logits,
                                     const float* __restrict__ source_p,
                                     const int*   __restrict__ x_t,
                                     const float* __restrict__ t_arr,
                                     float* __restrict__ out,
                                     int V) {
    const int n   = blockIdx.x;      // token index (one CTA per token)
    const int tid = threadIdx.x;
    const int nthreads = blockDim.x; // 256
    const int lane = tid & 31;
    const int warp = tid >> 5;

    __shared__ float swv[8];   // per-warp best value
    __shared__ int   swi[8];   // per-warp best index
    __shared__ float sws[8];   // per-warp partial sum of source_p

    const float* lrow = logits + (size_t)n * V;
    float* orow = out + (size_t)n * V;

    // --- Zero output row (harness poisons d_out) ---
    {
        float4* o4 = reinterpret_cast<float4*>(orow);
        int nvec = V >> 2;
        for (int i = tid; i < nvec; i += nthreads)
            o4[i] = make_float4(0.f, 0.f, 0.f, 0.f);
    }

    // --- Gumbel-argmax over this token's V logits + partial sum of source_p ---
    float best = -CUDART_INF_F;
    int   bidx = 0x7fffffff;
    float psum = 0.f;
    for (int v = tid; v < V; v += nthreads) {
        uint32_t idx = (uint32_t)n * (uint32_t)V + (uint32_t)v;
        float g = jax_gumbel_part(idx);
        float score = lrow[v] + g;
        if (score > best || (score == best && v < bidx)) {
            best = score;
            bidx = v;
        }
        psum += source_p[v];
    }

    // warp-level reduction (no barriers)
#pragma unroll
    for (int s = 16; s > 0; s >>= 1) {
        float ov = __shfl_down_sync(0xffffffffu, best, s);
        int   oi = __shfl_down_sync(0xffffffffu, bidx, s);
        float os = __shfl_down_sync(0xffffffffu, psum, s);
        if (ov > best || (ov == best && oi < bidx)) { best = ov; bidx = oi; }
        psum += os;
    }
    if (lane == 0) { swv[warp] = best; swi[warp] = bidx; sws[warp] = psum; }
    __syncthreads();

    // --- Final 8-way reduction + two-entry write (thread 0) ---
    if (tid == 0) {
        float fbest = swv[0];
        int   fbidx = swi[0];
        float S     = sws[0];
#pragma unroll
        for (int w = 1; w < 8; w++) {
            float ov = swv[w];
            int   oi = swi[w];
            if (ov > fbest || (ov == fbest && oi < fbidx)) { fbest = ov; fbidx = oi; }
            S += sws[w];
        }
        int x1 = fbidx;
        int xt = x_t[n];
        if (x1 != xt) {
            float t    = t_arr[0];
            float omt  = 1.0f - t;
            float spx1 = source_p[x1] / S;
            float spxt = source_p[xt] / S;
            float pt_xt = omt * spxt;          // p_t[xt]   (delta term is 0)
            float pt_x1 = omt * spx1 + t;      // p_t[x1]
            float pd_x1 = 1.0f - spx1;         // p_t_dot[x1]
            float pd_xt = -spxt;               // p_t_dot[xt]
            float j  = fmaxf(pt_xt * pd_x1 - pd_xt * pt_x1, 0.0f);
            float u  = j / (pt_x1 + EPSF);
            orow[x1] =  u;
            orow[xt] = -u;
        }
        // x1 == xt: row stays identically zero.
    }
}

extern "C" void kernel_launch(void* const* d_in, const int* in_sizes, int n_in,
                              void* d_out, int out_size) {
    // Bind inputs by element count (all four sizes are distinct for this
    // problem: logits=N*V, source_p=V, x_t=N, t=1) — robust to metadata
    // ordering. Falls back to positional if the pattern doesn't hold.
    int li = 0, spi = 1, xti = 2, ti = 3;
    if (n_in == 4) {
        // logits = largest; t = size 1; of the remaining two, source_p is the
        // larger (V) and x_t the smaller (N).
        int order[4] = {0, 1, 2, 3};
        // simple selection sort by size descending
        for (int a = 0; a < 4; a++)
            for (int b = a + 1; b < 4; b++)
                if (in_sizes[order[b]] > in_sizes[order[a]]) {
                    int tmp = order[a]; order[a] = order[b]; order[b] = tmp;
                }
        li  = order[0];   // N*V
        spi = order[1];   // V
        xti = order[2];   // N
        ti  = order[3];   // 1
    }

    const float* logits   = (const float*)d_in[li];
    const float* source_p = (const float*)d_in[spi];
    const int*   x_t      = (const int*)d_in[xti];
    const float* t_arr    = (const float*)d_in[ti];
    float* out = (float*)d_out;

    int total = in_sizes[li];     // N * V
    int V     = in_sizes[spi];    // vocab size
    int N     = total / V;        // tokens

    kinetic_euler_kernel<<<N, 256>>>(logits, source_p, x_t, t_arr, out, V);
}

// round 5
// speedup vs baseline: 1.0960x; 1.0960x over previous
#include <cuda_runtime.h>
#include <cstdint>
#include <math_constants.h>

// ============================================================================
// KineticOptimalDiscreteEulerSolver — collapsed 2-sparse form (R5 = R4 rerun).
//
// out[n] row is zero except (when x1 != x_t):
//   out[x1] = +u, out[x_t] = -u,
//   u = max(p_t[xt]*pd[x1] - pd[xt]*p_t[x1], 0) / (p_t[x1] + EPS)
// with p_t/pd built from the normalized source distribution and t.
//
// x1 = jax.random.categorical(jax.random.key(1), logits), partitionable
// threefry stream:
//   (o0,o1) = threefry2x32(key=(0,1), counter=(0, flat_idx)); bits = o0^o1
//   uniform = max(tiny, bitcast((bits>>9)|0x3f800000) - 1)
//   gumbel  = -log(-log(uniform));  argmax(logits+gumbel), first-index ties.
//
// vs R3 (6.94us passing): 1024 thr/CTA (1 elem/thread, 8 warps/SMSP for
// latency hiding), outer log via __logf (abs-error-only requirement), packed
// u64 argmax key, prefetched x_t/t.
// ============================================================================

#define TINYF 1.17549435e-38f
#define EPSF  1e-8f

__device__ __forceinline__ uint32_t rotl32(uint32_t x, int r) {
    return (x << r) | (x >> (32 - r));
}

// Threefry-2x32, 20 rounds, key (0, 1)
__device__ __forceinline__ void threefry2x32_key01(uint32_t c0, uint32_t c1,
                                                   uint32_t& o0, uint32_t& o1) {
    const uint32_t ks0 = 0u;
    const uint32_t ks1 = 1u;
    const uint32_t ks2 = 0x1BD11BDAu ^ ks0 ^ ks1;  // 0x1BD11BDB
    uint32_t x0 = c0 + ks0;
    uint32_t x1 = c1 + ks1;

#define TF_ROUND(r) { x0 += x1; x1 = rotl32(x1, r); x1 ^= x0; }
#define TF_G0 TF_ROUND(13) TF_ROUND(15) TF_ROUND(26) TF_ROUND(6)
#define TF_G1 TF_ROUND(17) TF_ROUND(29) TF_ROUND(16) TF_ROUND(24)

    TF_G0  x0 += ks1; x1 += ks2 + 1u;
    TF_G1  x0 += ks2; x1 += ks0 + 2u;
    TF_G0  x0 += ks0; x1 += ks1 + 3u;
    TF_G1  x0 += ks1; x1 += ks2 + 4u;
    TF_G0  x0 += ks2; x1 += ks0 + 5u;

#undef TF_ROUND
#undef TF_G0
#undef TF_G1
    o0 = x0;
    o1 = x1;
}

// Partitionable-threefry gumbel for flat element index idx (< 2^32):
// counter = (0, idx); word = o0 ^ o1.
// Inner log must be accurate-relative (u->1 => w->0); outer log only needs
// small absolute error => MUFU-based __logf.
__device__ __forceinline__ float jax_gumbel_part(uint32_t idx) {
    uint32_t o0, o1;
    threefry2x32_key01(0u, idx, o0, o1);
    uint32_t bits = o0 ^ o1;
    float f = __uint_as_float((bits >> 9) | 0x3f800000u) - 1.0f;
    float u = fmaxf(TINYF, f);
    float w = -logf(u);          // accurate (relative error matters)
    return -__logf(w);           // fast (absolute error ~2e-7 is harmless)
}

// Monotone float->uint32 mapping for unsigned compare (total order).
__device__ __forceinline__ uint32_t float_mono(float f) {
    uint32_t b = __float_as_uint(f);
    return (b & 0x80000000u) ? ~b : (b | 0x80000000u);
}

__global__ void __launch_bounds__(1024, 1)
kinetic_euler_kernel(const float* __restrict__ logits,
                     const float* __restrict__ source_p,
                     const int*   __restrict__ x_t,
                     const float* __restrict__ t_arr,
                     float* __restrict__ out,
                     int V) {
    const int n   = blockIdx.x;       // token index
    const int tid = threadIdx.x;
    const int nthreads = blockDim.x;  // 1024 (V>=1024 path)
    const int lane = tid & 31;
    const int warp = tid >> 5;

    __shared__ unsigned long long skey[32];
    __shared__ float ssum[32];

    // Defensive init (only matters if blockDim < 1024 fallback is taken).
    if (tid < 32) { skey[tid] = 0ull; ssum[tid] = 0.f; }

    const float* lrow = logits + (size_t)n * V;
    float* orow = out + (size_t)n * V;

    // Prefetch tail operands early (hide L2/DRAM latency behind compute).
    int   xt_pre = 0;
    float t_pre  = 0.f;
    if (tid == 0) { xt_pre = x_t[n]; t_pre = t_arr[0]; }

    // Zero output row (harness poisons d_out). V==1024 -> single pass.
    for (int v = tid; v < V; v += nthreads)
        orow[v] = 0.f;

    // Gumbel-argmax + source_p partial sum. One element per thread (V=1024).
    // key64 = mono(score)<<32 | ~v  -> max(key) == (max score, min index).
    unsigned long long key = 0ull;   // any real score (sign bit set in mono)
                                     // beats the 0 sentinel
    float psum = 0.f;
    for (int v = tid; v < V; v += nthreads) {
        float g = jax_gumbel_part((uint32_t)n * (uint32_t)V + (uint32_t)v);
        float score = lrow[v] + g;
        unsigned long long k =
            ((unsigned long long)float_mono(score) << 32) |
            (unsigned long long)(~(uint32_t)v);
        if (k > key) key = k;
        psum += source_p[v];
    }

    // Warp reduction (no barriers).
#pragma unroll
    for (int s = 16; s > 0; s >>= 1) {
        unsigned long long ok = __shfl_down_sync(0xffffffffu, key, s);
        float os = __shfl_down_sync(0xffffffffu, psum, s);
        if (ok > key) key = ok;
        psum += os;
    }
    if (lane == 0) { skey[warp] = key; ssum[warp] = psum; }
    __syncthreads();

    // Warp 0 reduces the per-warp partials.
    if (warp == 0) {
        key  = skey[lane];
        psum = ssum[lane];
#pragma unroll
        for (int s = 16; s > 0; s >>= 1) {
            unsigned long long ok = __shfl_down_sync(0xffffffffu, key, s);
            float os = __shfl_down_sync(0xffffffffu, psum, s);
            if (ok > key) key = ok;
            psum += os;
        }
        if (lane == 0) {
            int   x1 = (int)(~(uint32_t)(key & 0xffffffffull));
            float S  = psum;
            int   xt = xt_pre;
            if (x1 != xt) {
                float t    = t_pre;
                float omt  = 1.0f - t;
                float spx1 = source_p[x1] / S;
                float spxt = source_p[xt] / S;
                float pt_xt = omt * spxt;          // p_t[xt]
                float pt_x1 = omt * spx1 + t;      // p_t[x1]
                float pd_x1 = 1.0f - spx1;         // p_t_dot[x1]
                float pd_xt = -spxt;               // p_t_dot[xt]
                float j  = fmaxf(pt_xt * pd_x1 - pd_xt * pt_x1, 0.0f);
                float u  = j / (pt_x1 + EPSF);
                orow[x1] =  u;
                orow[xt] = -u;
            }
            // x1 == xt: row stays identically zero.
        }
    }
}

extern "C" void kernel_launch(void* const* d_in, const int* in_sizes, int n_in,
                              void* d_out, int out_size) {
    // Bind inputs by element count (sizes distinct: N*V > V > N > 1).
    int li = 0, spi = 1, xti = 2, ti = 3;
    if (n_in == 4) {
        int order[4] = {0, 1, 2, 3};
        for (int a = 0; a < 4; a++)
            for (int b = a + 1; b < 4; b++)
                if (in_sizes[order[b]] > in_sizes[order[a]]) {
                    int tmp = order[a]; order[a] = order[b]; order[b] = tmp;
                }
        li  = order[0];   // N*V
        spi = order[1];   // V
        xti = order[2];   // N
        ti  = order[3];   // 1
    }

    const float* logits   = (const float*)d_in[li];
    const float* source_p = (const float*)d_in[spi];
    const int*   x_t      = (const int*)d_in[xti];
    const float* t_arr    = (const float*)d_in[ti];
    float* out = (float*)d_out;

    int total = in_sizes[li];     // N * V
    int V     = in_sizes[spi];    // vocab size
    int N     = total / V;        // tokens

    int threads = (V >= 1024) ? 1024 : ((V + 31) & ~31);
    if (threads < 32) threads = 32;
    kinetic_euler_kernel<<<N, threads>>>(logits, source_p, x_t, t_arr, out, V);
}